// round 1
// baseline (speedup 1.0000x reference)
#include <cuda_runtime.h>

// GAT layer, shapes fixed by setup_inputs: n=16, t=12, N=64, c=o=64.
// adj is dead code in the reference. The tile/cat(dim=1)/view sequence makes
// a_input degenerate; see derivation in analysis. Everything reduces to:
//   wa0 = W @ a[:64], wa1 = W @ a[64:]            (64-vectors)
//   p[T,u] = inp[n,T,u,:]·wa0,  q[T,u] = inp[n,T,u,:]·wa1
//   tt<6 : e[v,w] = lrelu( (p+q)[2tt+(v>=32), (2v+(w>=32))%64] )
//   tt>=6: e[v,w] = lrelu( p[2(tt-6)+(v>=32),(2w)%64] + q[...,(2w+1)%64] )
//   softmax over w; h_prime = (attn @ inp[n,tt]) @ W; elu.
// Output = concat( elu(h_prime)[16,12,64,64], attention[16,12,64,64] ).

#define NT 12
#define LRELU_A 0.2f

__device__ __forceinline__ float wsum(float v) {
#pragma unroll
    for (int s = 16; s; s >>= 1) v += __shfl_xor_sync(0xffffffffu, v, s);
    return v;
}
__device__ __forceinline__ float wmax(float v) {
#pragma unroll
    for (int s = 16; s; s >>= 1) v = fmaxf(v, __shfl_xor_sync(0xffffffffu, v, s));
    return v;
}
__device__ __forceinline__ float elu1(float x) {
    return x > 0.0f ? x : expm1f(x);
}

__global__ void __launch_bounds__(256, 8) gat_kernel(
    const float* __restrict__ inp, const float* __restrict__ W,
    const float* __restrict__ a, float* __restrict__ out_h,
    float* __restrict__ out_att)
{
    const int b    = blockIdx.x;          // 0..191  (= nn*12 + tt)
    const int tt   = b % NT;
    const int nn   = b / NT;
    const int tid  = threadIdx.x;
    const int lane = tid & 31;
    const int warp = tid >> 5;            // 0..7

    __shared__ float a_s[128];
    __shared__ float wa0[64], wa1[64];
    __shared__ float p0[64], q0[64], p1[64], q1[64];
    __shared__ float s0[64], s1[64];      // attn weights (aL/aH) or attn rows
    __shared__ float v0[64], v1[64];      // col sums / attn@inp vectors
    __shared__ float h0[64], h1[64];      // gemv results (h_prime rows/S vectors)

    if (tid < 128) a_s[tid] = a[tid];
    __syncthreads();

    // --- wa0[c] = sum_o W[c][o]*a[o];  wa1[c] = sum_o W[c][o]*a[64+o] ---
#pragma unroll
    for (int i = 0; i < 8; ++i) {
        int c = warp * 8 + i;
        float w0 = W[c * 64 + lane];
        float w1 = W[c * 64 + 32 + lane];
        float r0 = wsum(w0 * a_s[lane] + w1 * a_s[32 + lane]);
        float r1 = wsum(w0 * a_s[64 + lane] + w1 * a_s[96 + lane]);
        if (lane == 0) { wa0[c] = r0; wa1[c] = r1; }
    }
    __syncthreads();

    const bool first = (tt < 6);
    const int  T0    = first ? 2 * tt : 2 * (tt - 6);
    const float* __restrict__ inpT0 = inp + ((size_t)nn * NT + T0) * 4096;
    const float* __restrict__ inpT1 = inpT0 + 4096;
    const float* __restrict__ inpC  = inp + ((size_t)nn * NT + tt) * 4096;

    // --- p/q for time slices T0, T1: warp-cooperative row dots (coalesced) ---
#pragma unroll
    for (int i = 0; i < 8; ++i) {
        int u = warp * 8 + i;
        float x0 = inpT0[u * 64 + lane], x1 = inpT0[u * 64 + 32 + lane];
        float pv = wsum(x0 * wa0[lane] + x1 * wa0[32 + lane]);
        float qv = wsum(x0 * wa1[lane] + x1 * wa1[32 + lane]);
        if (lane == 0) { p0[u] = pv; q0[u] = qv; }
        x0 = inpT1[u * 64 + lane]; x1 = inpT1[u * 64 + 32 + lane];
        pv = wsum(x0 * wa0[lane] + x1 * wa0[32 + lane]);
        qv = wsum(x0 * wa1[lane] + x1 * wa1[32 + lane]);
        if (lane == 0) { p1[u] = pv; q1[u] = qv; }
    }
    __syncthreads();

    const size_t obase = (size_t)b * 4096;

    if (first) {
        // e row for v: two values (w<32 vs w>=32); softmax is closed-form.
        if (tid < 64) {
            int v = tid;
            const float* pp = (v < 32) ? p0 : p1;
            const float* qq = (v < 32) ? q0 : q1;
            int i0 = (2 * v) & 63, i1 = (2 * v + 1) & 63;
            float eL = pp[i0] + qq[i0]; eL = eL > 0.f ? eL : LRELU_A * eL;
            float eH = pp[i1] + qq[i1]; eH = eH > 0.f ? eH : LRELU_A * eH;
            float m  = fmaxf(eL, eH);
            float wl = expf(eL - m), wh = expf(eH - m);
            float den = 32.0f * (wl + wh);
            s0[v] = wl / den;   // attn value for w<32
            s1[v] = wh / den;   // attn value for w>=32
        } else if (tid < 192) {
            // column sums of inp[tt] over rows [0,32) and [32,64)
            int c = tid & 63;
            bool hi = (tid >= 128);
            const float* src = inpC + (hi ? 32 * 64 : 0) + c;
            float s = 0.f;
#pragma unroll
            for (int w = 0; w < 32; ++w) s += src[w * 64];
            (hi ? v1 : v0)[c] = s;
        }
        __syncthreads();
        // S_L[o] = rL @ W ; S_H[o] = rH @ W
        if (tid < 128) {
            int o = tid & 63;
            bool hi = (tid >= 64);
            const float* vv = hi ? v1 : v0;
            float s = 0.f;
#pragma unroll
            for (int c = 0; c < 64; ++c) s += vv[c] * W[c * 64 + o];
            (hi ? h1 : h0)[o] = s;
        }
        __syncthreads();
        // writes: h_prime[v][o] = aL[v]*S_L[o] + aH[v]*S_H[o], elu; attn[v][w]
#pragma unroll
        for (int r = 0; r < 4; ++r) {
            int idx = r * 1024 + tid * 4;
            int v = idx >> 6, o = idx & 63;
            float aL = s0[v], aH = s1[v];
            float4 oh;
            oh.x = elu1(aL * h0[o + 0] + aH * h1[o + 0]);
            oh.y = elu1(aL * h0[o + 1] + aH * h1[o + 1]);
            oh.z = elu1(aL * h0[o + 2] + aH * h1[o + 2]);
            oh.w = elu1(aL * h0[o + 3] + aH * h1[o + 3]);
            *reinterpret_cast<float4*>(out_h + obase + idx) = oh;
            float av = (o < 32) ? aL : aH;
            float4 oa; oa.x = av; oa.y = av; oa.z = av; oa.w = av;
            *reinterpret_cast<float4*>(out_att + obase + idx) = oa;
        }
    } else {
        // tt >= 6: two distinct e rows (v<32 vs v>=32)
        if (tid < 128) {
            int w = tid & 63;
            bool hi = (tid >= 64);
            const float* pp = hi ? p1 : p0;
            const float* qq = hi ? q1 : q0;
            float e = pp[(2 * w) & 63] + qq[(2 * w + 1) & 63];
            e = e > 0.f ? e : LRELU_A * e;
            (hi ? s1 : s0)[w] = e;
        }
        __syncthreads();
        // softmax over 64 values for each row (warp 0 -> lo, warp 1 -> hi)
        if (warp < 2) {
            float* e = warp ? s1 : s0;
            float x0 = e[lane], x1 = e[lane + 32];
            float m = wmax(fmaxf(x0, x1));
            float e0 = expf(x0 - m), e1 = expf(x1 - m);
            float den = wsum(e0 + e1);
            e[lane]      = e0 / den;
            e[lane + 32] = e1 / den;
        }
        __syncthreads();
        // u[c] = attn_row @ inp[tt][:, c]   (coalesced global reads)
        if (tid < 128) {
            int c = tid & 63;
            bool hi = (tid >= 64);
            const float* att = hi ? s1 : s0;
            float s = 0.f;
#pragma unroll
            for (int w = 0; w < 64; ++w) s += att[w] * inpC[w * 64 + c];
            (hi ? v1 : v0)[c] = s;
        }
        __syncthreads();
        // hp[o] = u @ W, then elu
        if (tid < 128) {
            int o = tid & 63;
            bool hi = (tid >= 64);
            const float* vv = hi ? v1 : v0;
            float s = 0.f;
#pragma unroll
            for (int c = 0; c < 64; ++c) s += vv[c] * W[c * 64 + o];
            (hi ? h1 : h0)[o] = elu1(s);
        }
        __syncthreads();
#pragma unroll
        for (int r = 0; r < 4; ++r) {
            int idx = r * 1024 + tid * 4;
            int v = idx >> 6, o = idx & 63;
            const float* hr = (v < 32) ? h0 : h1;
            const float* ar = (v < 32) ? s0 : s1;
            float4 oh; oh.x = hr[o]; oh.y = hr[o + 1]; oh.z = hr[o + 2]; oh.w = hr[o + 3];
            *reinterpret_cast<float4*>(out_h + obase + idx) = oh;
            float4 oa; oa.x = ar[o]; oa.y = ar[o + 1]; oa.z = ar[o + 2]; oa.w = ar[o + 3];
            *reinterpret_cast<float4*>(out_att + obase + idx) = oa;
        }
    }
}

extern "C" void kernel_launch(void* const* d_in, const int* in_sizes, int n_in,
                              void* d_out, int out_size) {
    const float* inp = (const float*)d_in[0];   // [16,12,64,64]
    // d_in[1] = adj : dead code in the reference
    const float* W   = (const float*)d_in[2];   // [64,64]
    const float* a   = (const float*)d_in[3];   // [128,1]
    float* out = (float*)d_out;                 // elu(h_prime) then attention
    int nt = in_sizes[0] / 4096;                // n*t = 192
    gat_kernel<<<nt, 256>>>(inp, W, a, out, out + out_size / 2);
}

// round 2
// speedup vs baseline: 1.2179x; 1.2179x over previous
#include <cuda_runtime.h>

// GAT layer, shapes fixed: n=16, t=12, N=64, c=o=64. adj is dead code.
// Degenerate tile/cat(dim=1)/view algebra (verified R1, rel_err 4e-7):
//   wa0 = W @ a[:64], wa1 = W @ a[64:]
//   p[T,u] = inp[n,T,u,:]·wa0,  q[T,u] = inp[n,T,u,:]·wa1
//   tt<6 : e[v,w] = lrelu( (p+q)[2tt+(v>=32), (2v+(w>=32))%64] )  -> 2 distinct
//          values per softmax row -> closed-form softmax.
//   tt>=6: e[v,w] = lrelu( p[2(tt-6)+(v>=32),(2w)%64] + q[...,(2w+1)%64] )
//          -> 2 distinct attention rows.
//   h_prime = (attn @ inp[n,tt]) @ W; elu.
// R2: all reductions as serial FMA dots over padded (stride-65) transposed
// shared tiles; no warp shuffles on the critical path.

#define NT 12
#define LRELU_A 0.2f
#define TS 65   // padded tile stride (odd -> conflict-free stride-65 reads)

__device__ __forceinline__ float wsum(float v) {
#pragma unroll
    for (int s = 16; s; s >>= 1) v += __shfl_xor_sync(0xffffffffu, v, s);
    return v;
}
__device__ __forceinline__ float wmax(float v) {
#pragma unroll
    for (int s = 16; s; s >>= 1) v = fmaxf(v, __shfl_xor_sync(0xffffffffu, v, s));
    return v;
}
__device__ __forceinline__ float elu1(float x) { return x > 0.0f ? x : expm1f(x); }

__global__ void __launch_bounds__(256) gat_kernel(
    const float* __restrict__ inp, const float* __restrict__ W,
    const float* __restrict__ a, float* __restrict__ out_h,
    float* __restrict__ out_att)
{
    // Transposed padded tiles: tile[c*TS + u] = src[u*64 + c]
    __shared__ float tA[64 * TS];
    __shared__ float tB[64 * TS];
    __shared__ float a_s[128], wa0[64], wa1[64];
    __shared__ float p0[64], q0[64], p1[64], q1[64];
    __shared__ __align__(16) float s0[64], s1[64];
    __shared__ float v0[64], v1[64];
    __shared__ __align__(16) float h0[64], h1[64];

    const int b    = blockIdx.x;          // nn*12 + tt
    const int tt   = b % NT;
    const int nn   = b / NT;
    const int tid  = threadIdx.x;
    const int lane = tid & 31;
    const int warp = tid >> 5;

    // ---- stage 0: a -> smem, W^T -> tA (coalesced LDG, conflict-free STS) --
    if (tid < 128) a_s[tid] = a[tid];
#pragma unroll
    for (int i = 0; i < 16; ++i) {
        int idx = tid + i * 256;                  // idx = c*64 + o
        tA[(idx & 63) * TS + (idx >> 6)] = W[idx]; // tA[o*TS + c] = W[c][o]
    }
    __syncthreads();

    // ---- stage 1: wa0[c] = sum_o W[c][o]*a[o], wa1 with a[64:] -------------
    if (tid < 128) {
        int c = tid & 63;
        const float* av = a_s + ((tid >> 6) << 6);
        float r0 = 0.f, r1 = 0.f, r2 = 0.f, r3 = 0.f;
#pragma unroll
        for (int o = 0; o < 64; o += 4) {
            r0 = fmaf(tA[(o + 0) * TS + c], av[o + 0], r0);
            r1 = fmaf(tA[(o + 1) * TS + c], av[o + 1], r1);
            r2 = fmaf(tA[(o + 2) * TS + c], av[o + 2], r2);
            r3 = fmaf(tA[(o + 3) * TS + c], av[o + 3], r3);
        }
        ((tid < 64) ? wa0 : wa1)[c] = (r0 + r1) + (r2 + r3);
    }
    __syncthreads();

    const bool first = (tt < 6);
    const int  T0    = first ? 2 * tt : 2 * (tt - 6);
    const float* __restrict__ iT0 = inp + ((size_t)nn * NT + T0) * 4096;
    const float* __restrict__ iT1 = iT0 + 4096;
    const float* __restrict__ iC  = inp + ((size_t)nn * NT + tt) * 4096;

    // ---- stage 2: T0 -> tA, T1 -> tB (transposed) ---------------------------
#pragma unroll
    for (int i = 0; i < 16; ++i) {
        int idx = tid + i * 256;
        int u = idx >> 6, c = idx & 63;
        tA[c * TS + u] = iT0[idx];
        tB[c * TS + u] = iT1[idx];
    }
    __syncthreads();

    // ---- stage 3: p/q — 256 threads, one dot each --------------------------
    {
        int u = tid & 63, sel = tid >> 6;              // uniform per warp-pair
        const float* tile = (sel & 2) ? tB : tA;
        const float* wv   = (sel & 1) ? wa1 : wa0;
        float r0 = 0.f, r1 = 0.f, r2 = 0.f, r3 = 0.f;
#pragma unroll
        for (int c = 0; c < 64; c += 4) {
            r0 = fmaf(tile[(c + 0) * TS + u], wv[c + 0], r0);
            r1 = fmaf(tile[(c + 1) * TS + u], wv[c + 1], r1);
            r2 = fmaf(tile[(c + 2) * TS + u], wv[c + 2], r2);
            r3 = fmaf(tile[(c + 3) * TS + u], wv[c + 3], r3);
        }
        float r = (r0 + r1) + (r2 + r3);
        float* dst = (sel == 0) ? p0 : (sel == 1) ? q0 : (sel == 2) ? p1 : q1;
        dst[u] = r;
    }
    __syncthreads();

    // ---- stage 4: reload iC -> tA, W^T -> tB, overlapped with e/softmax ----
#pragma unroll
    for (int i = 0; i < 16; ++i) {
        int idx = tid + i * 256;
        int u = idx >> 6, c = idx & 63;
        tA[c * TS + u] = iC[idx];          // tA[c*TS+w] = inpC[w][c]
        tB[c * TS + u] = W[idx];           // tB[o*TS+c] = W[c][o]
    }

    const size_t obase = (size_t)b * 4096;

    if (first) {
        // closed-form softmax: 2 distinct values per row
        if (tid < 64) {
            int v = tid;
            const float* pp = (v < 32) ? p0 : p1;
            const float* qq = (v < 32) ? q0 : q1;
            int i0 = (2 * v) & 63, i1 = (2 * v + 1) & 63;
            float eL = pp[i0] + qq[i0]; eL = eL > 0.f ? eL : LRELU_A * eL;
            float eH = pp[i1] + qq[i1]; eH = eH > 0.f ? eH : LRELU_A * eH;
            float m  = fmaxf(eL, eH);
            float wl = expf(eL - m), wh = expf(eH - m);
            float den = 32.0f * (wl + wh);
            s0[v] = wl / den;
            s1[v] = wh / den;
        }
        __syncthreads();
        // column sums of inpC over rows [0,32) and [32,64)
        if (tid < 128) {
            int c = tid & 63; bool hi = (tid >= 64);
            const float* base = tA + c * TS + (hi ? 32 : 0);
            float r0 = 0.f, r1 = 0.f, r2 = 0.f, r3 = 0.f;
#pragma unroll
            for (int w = 0; w < 32; w += 4) {
                r0 += base[w + 0]; r1 += base[w + 1];
                r2 += base[w + 2]; r3 += base[w + 3];
            }
            (hi ? v1 : v0)[c] = (r0 + r1) + (r2 + r3);
        }
        __syncthreads();
        // S[o] = v @ W (from shared W^T)
        if (tid < 128) {
            int o = tid & 63; bool hi = (tid >= 64);
            const float* vv = hi ? v1 : v0;
            const float* wr = tB + o * TS;
            float r0 = 0.f, r1 = 0.f, r2 = 0.f, r3 = 0.f;
#pragma unroll
            for (int c = 0; c < 64; c += 4) {
                r0 = fmaf(vv[c + 0], wr[c + 0], r0);
                r1 = fmaf(vv[c + 1], wr[c + 1], r1);
                r2 = fmaf(vv[c + 2], wr[c + 2], r2);
                r3 = fmaf(vv[c + 3], wr[c + 3], r3);
            }
            (hi ? h1 : h0)[o] = (r0 + r1) + (r2 + r3);
        }
        __syncthreads();
        // h_prime[v][o] = aL[v]*S_L[o] + aH[v]*S_H[o], elu; attn[v][w]
#pragma unroll
        for (int r = 0; r < 4; ++r) {
            int idx = r * 1024 + tid * 4;
            int v = idx >> 6, o = idx & 63;
            float aL = s0[v], aH = s1[v];
            float4 oh;
            oh.x = elu1(fmaf(aL, h0[o + 0], aH * h1[o + 0]));
            oh.y = elu1(fmaf(aL, h0[o + 1], aH * h1[o + 1]));
            oh.z = elu1(fmaf(aL, h0[o + 2], aH * h1[o + 2]));
            oh.w = elu1(fmaf(aL, h0[o + 3], aH * h1[o + 3]));
            *reinterpret_cast<float4*>(out_h + obase + idx) = oh;
            float av = (o < 32) ? aL : aH;
            float4 oa; oa.x = av; oa.y = av; oa.z = av; oa.w = av;
            *reinterpret_cast<float4*>(out_att + obase + idx) = oa;
        }
    } else {
        // two distinct e rows (v<32 vs v>=32)
        if (tid < 128) {
            int w = tid & 63; bool hi = (tid >= 64);
            const float* pp = hi ? p1 : p0;
            const float* qq = hi ? q1 : q0;
            float e = pp[(2 * w) & 63] + qq[(2 * w + 1) & 63];
            (hi ? s1 : s0)[w] = e > 0.f ? e : LRELU_A * e;
        }
        __syncthreads();
        // softmax over 64 per row (warp 0 -> lo, warp 1 -> hi)
        if (warp < 2) {
            float* e = warp ? s1 : s0;
            float x0 = e[lane], x1 = e[lane + 32];
            float m = wmax(fmaxf(x0, x1));
            float e0 = expf(x0 - m), e1 = expf(x1 - m);
            float den = wsum(e0 + e1);
            e[lane]      = e0 / den;
            e[lane + 32] = e1 / den;
        }
        __syncthreads();
        // u[c] = attn_row @ inpC[:, c] (from shared tile)
        if (tid < 128) {
            int c = tid & 63; bool hi = (tid >= 64);
            const float* att  = hi ? s1 : s0;
            const float* base = tA + c * TS;
            float r0 = 0.f, r1 = 0.f, r2 = 0.f, r3 = 0.f;
#pragma unroll
            for (int w = 0; w < 64; w += 4) {
                r0 = fmaf(att[w + 0], base[w + 0], r0);
                r1 = fmaf(att[w + 1], base[w + 1], r1);
                r2 = fmaf(att[w + 2], base[w + 2], r2);
                r3 = fmaf(att[w + 3], base[w + 3], r3);
            }
            (hi ? v1 : v0)[c] = (r0 + r1) + (r2 + r3);
        }
        __syncthreads();
        // hp[o] = u @ W (shared W^T), elu
        if (tid < 128) {
            int o = tid & 63; bool hi = (tid >= 64);
            const float* vv = hi ? v1 : v0;
            const float* wr = tB + o * TS;
            float r0 = 0.f, r1 = 0.f, r2 = 0.f, r3 = 0.f;
#pragma unroll
            for (int c = 0; c < 64; c += 4) {
                r0 = fmaf(vv[c + 0], wr[c + 0], r0);
                r1 = fmaf(vv[c + 1], wr[c + 1], r1);
                r2 = fmaf(vv[c + 2], wr[c + 2], r2);
                r3 = fmaf(vv[c + 3], wr[c + 3], r3);
            }
            (hi ? h1 : h0)[o] = elu1((r0 + r1) + (r2 + r3));
        }
        __syncthreads();
#pragma unroll
        for (int r = 0; r < 4; ++r) {
            int idx = r * 1024 + tid * 4;
            int v = idx >> 6, o = idx & 63;
            const float* hr = (v < 32) ? h0 : h1;
            const float* ar = (v < 32) ? s0 : s1;
            float4 oh; oh.x = hr[o]; oh.y = hr[o + 1]; oh.z = hr[o + 2]; oh.w = hr[o + 3];
            *reinterpret_cast<float4*>(out_h + obase + idx) = oh;
            float4 oa; oa.x = ar[o]; oa.y = ar[o + 1]; oa.z = ar[o + 2]; oa.w = ar[o + 3];
            *reinterpret_cast<float4*>(out_att + obase + idx) = oa;
        }
    }
}

extern "C" void kernel_launch(void* const* d_in, const int* in_sizes, int n_in,
                              void* d_out, int out_size) {
    const float* inp = (const float*)d_in[0];   // [16,12,64,64]
    // d_in[1] = adj : dead code in the reference
    const float* W   = (const float*)d_in[2];   // [64,64]
    const float* a   = (const float*)d_in[3];   // [128,1]
    float* out = (float*)d_out;                 // elu(h_prime) then attention
    int nt = in_sizes[0] / 4096;                // n*t = 192
    gat_kernel<<<nt, 256>>>(inp, W, a, out, out + out_size / 2);
}